// round 4
// baseline (speedup 1.0000x reference)
#include <cuda_runtime.h>
#include <cstdint>

// Problem constants
#define NTOK    8192            // 1024 * 8 tokens
#define ROWS    81920           // NTOK * 10 groups
#define NCOLS   4096
#define CT      128             // column tiles of 32
#define JT      32              // columns per tile
#define RB      8               // row blocks
#define ROWS_PER_RB (ROWS / RB) // 10240
#define TAB_FLOATS (5 * 256 * JT)          // 40960 (5 groups x 256 sym-halved entries x 32 cols)
#define SMEM_BYTES ((TAB_FLOATS + 45 * JT) * 4)  // 169600 B

// Scratch (allocation-free: __device__ globals)
__device__ uint32_t            g_rowdata[(size_t)ROWS * 12];      // 48 B / row: 5 offsets + 5 sign floats + pad
__device__ unsigned long long  g_part[(size_t)ROWS * CT];         // per-(row, col-tile) packed (key<<32 | 4095-col)

// ---------------------------------------------------------------------------
// Kernel 1: signs + per-row table addressing records
// y[c][k] = x0*S[c,0,k] + x1*S[c,1,k] - T[c,k] - 1e-4 ; bit = (y < 0)
// Row r = token*10 + g covers flat dims p=0..44, p = (c-3g)*15 + k.
// Split 45 bits into 5 groups of 9; apply V(~m) = -V(m) symmetry.
// ---------------------------------------------------------------------------
__global__ void k_signs(const float* __restrict__ x,
                        const float* __restrict__ S,
                        const float* __restrict__ T)
{
    int i = blockIdx.x * blockDim.x + threadIdx.x;
    if (i >= ROWS) return;
    int token = i / 10, g = i % 10;
    int a = token >> 3, b = token & 7;
    const float* xr = x + a * 480 + b * 60;

    unsigned long long mask = 0ull;
#pragma unroll
    for (int cl = 0; cl < 3; cl++) {
        int c = 3 * g + cl;
        float x0 = xr[c * 2 + 0];
        float x1 = xr[c * 2 + 1];
        const float* S0 = S + c * 30;        // S[c][0][*]
        const float* S1 = S0 + 15;           // S[c][1][*]
        const float* Tc = T + c * 15;
#pragma unroll
        for (int k = 0; k < 15; k++) {
            // match reference order/rounding as closely as possible (no fma contraction)
            float y = __fadd_rn(__fmul_rn(x0, S0[k]), __fmul_rn(x1, S1[k]));
            y = __fadd_rn(y, -Tc[k]);
            y = __fadd_rn(y, -1e-4f);
            if (y < 0.f) mask |= 1ull << (cl * 15 + k);
        }
    }

    uint32_t rec[12];
#pragma unroll
    for (int q = 0; q < 5; q++) {
        uint32_t m9 = (uint32_t)(mask >> (9 * q)) & 511u;
        uint32_t s  = m9 >> 8;                    // top bit => negate whole group sum
        uint32_t e  = s ? (m9 ^ 511u) : m9;       // 9-bit complement -> entry < 256
        rec[q]     = (uint32_t)(q * 8192 + e * JT);  // float-index into tab
        rec[5 + q] = __float_as_uint(s ? -1.f : 1.f);
    }
    rec[10] = 0; rec[11] = 0;
    uint4* dst = reinterpret_cast<uint4*>(g_rowdata + (size_t)i * 12);
    dst[0] = make_uint4(rec[0], rec[1], rec[2], rec[3]);
    dst[1] = make_uint4(rec[4], rec[5], rec[6], rec[7]);
    dst[2] = make_uint4(rec[8], rec[9], rec[10], rec[11]);
}

// ---------------------------------------------------------------------------
// Kernel 2: build sign-sum tables in SMEM, then scores + fused argmax.
// grid = 1024 CTAs: bid&127 = col tile (32 cols), bid>>7 = row block (10240 rows).
// One warp per row per 32-col tile: lane = column. All lanes share the row's
// table indices -> each LDS is a conflict-free 128B wavefront.
// ---------------------------------------------------------------------------
__global__ __launch_bounds__(512, 1)
void k_scores(const float* __restrict__ H)
{
    extern __shared__ float smem[];
    float* tab = smem;                 // [5][256][32]
    float* Ht  = smem + TAB_FLOATS;    // [45][32] staged H tile

    int ct = blockIdx.x & (CT - 1);
    int rb = blockIdx.x >> 7;
    int colbase = ct * JT;
    int tid = threadIdx.x;

    // Stage the 45 x 32 slice of H
    for (int i = tid; i < 45 * JT; i += 512)
        Ht[i] = H[(size_t)(i >> 5) * NCOLS + colbase + (i & 31)];
    __syncthreads();

    // Build tables: tab[q*8192 + e*32 + c] = sum_{d=0..8} (+/-)H[9q+d][col]
    // (bit8 of entry is implicitly 0 -> +1; bit=1 means -1)
    for (int cell = tid; cell < 5 * 8192; cell += 512) {
        int q = cell >> 13;
        int e = (cell >> 5) & 255;
        int c = cell & 31;
        const float* hq = Ht + (q * 9) * JT + c;
        float acc = 0.f;
#pragma unroll
        for (int d = 0; d < 9; d++) {
            float h = hq[d * JT];
            acc += ((e >> d) & 1) ? -h : h;
        }
        tab[cell] = acc;
    }
    __syncthreads();

    int warp = tid >> 5, lane = tid & 31;
    unsigned loCol = (unsigned)(4095 - (colbase + lane));  // complement: max picks SMALLEST col
    int r    = rb * ROWS_PER_RB + warp;
    int rend = rb * ROWS_PER_RB + ROWS_PER_RB;

#pragma unroll 4
    for (; r < rend; r += 16) {
        const uint4* rec = reinterpret_cast<const uint4*>(g_rowdata + (size_t)r * 12);
        uint4 A = rec[0];                                           // off0..off3
        uint4 B = rec[1];                                           // off4, sgn0, sgn1, sgn2
        uint2 Cc = *reinterpret_cast<const uint2*>(g_rowdata + (size_t)r * 12 + 8); // sgn3, sgn4

        float v =      __uint_as_float(B.y)  * tab[A.x + lane];
        v = fmaf(__uint_as_float(B.z),  tab[A.y + lane], v);
        v = fmaf(__uint_as_float(B.w),  tab[A.z + lane], v);
        v = fmaf(__uint_as_float(Cc.x), tab[A.w + lane], v);
        v = fmaf(__uint_as_float(Cc.y), tab[B.x + lane], v);

        // monotone float -> u32 key
        unsigned u   = __float_as_uint(v);
        unsigned key = u ^ ((unsigned)(((int)u) >> 31) | 0x80000000u);
        unsigned m    = __reduce_max_sync(0xffffffffu, key);
        unsigned ball = __ballot_sync(0xffffffffu, key == m);
        if (lane == (__ffs(ball) - 1))
            g_part[(size_t)r * CT + ct] =
                ((unsigned long long)m << 32) | (unsigned long long)loCol;
    }
}

// ---------------------------------------------------------------------------
// Kernel 3: merge 128 tile-winners per row, gather LUT, write output.
// One warp per row; lane loads 4 partials.
// ---------------------------------------------------------------------------
__global__ void k_merge(const float* __restrict__ LUT, float2* __restrict__ out)
{
    int wg   = (blockIdx.x * blockDim.x + threadIdx.x) >> 5;
    int lane = threadIdx.x & 31;
    if (wg >= ROWS) return;

    const unsigned long long* p = g_part + (size_t)wg * CT;
    unsigned long long best = p[lane];
    unsigned long long t;
    t = p[lane + 32]; if (t > best) best = t;
    t = p[lane + 64]; if (t > best) best = t;
    t = p[lane + 96]; if (t > best) best = t;

    unsigned hi = (unsigned)(best >> 32);
    unsigned lo = (unsigned)best;
    unsigned mhi  = __reduce_max_sync(0xffffffffu, hi);
    unsigned cand = (hi == mhi) ? lo : 0u;
    unsigned mlo  = __reduce_max_sync(0xffffffffu, cand);

    if (lane == 0) {
        int col = 4095 - (int)mlo;
        int g   = wg % 10;
        const float2* l2 = reinterpret_cast<const float2*>(LUT);
        out[wg] = l2[(size_t)g * NCOLS + col];
    }
}

// ---------------------------------------------------------------------------
extern "C" void kernel_launch(void* const* d_in, const int* in_sizes, int n_in,
                              void* d_out, int out_size)
{
    const float* x   = (const float*)d_in[0];
    const float* S   = (const float*)d_in[1];
    const float* T   = (const float*)d_in[2];
    const float* H   = (const float*)d_in[3];
    const float* LUT = (const float*)d_in[4];
    (void)in_sizes; (void)n_in; (void)out_size;

    cudaFuncSetAttribute(k_scores, cudaFuncAttributeMaxDynamicSharedMemorySize, SMEM_BYTES);

    k_signs<<<(ROWS + 255) / 256, 256>>>(x, S, T);
    k_scores<<<CT * RB, 512, SMEM_BYTES>>>(H);
    k_merge<<<(ROWS * 32 + 255) / 256, 256>>>(LUT, (float2*)d_out);
}

// round 5
// speedup vs baseline: 3.4725x; 3.4725x over previous
#include <cuda_runtime.h>
#include <cstdint>

// ---------------------------------------------------------------------------
// Problem constants
// ---------------------------------------------------------------------------
#define NTOK    8192            // 1024 * 8 tokens
#define ROWS    81920           // NTOK * 10 groups
#define NCOLS   4096
#define CT      128             // column tiles of 32
#define JT      32              // columns per tile
#define RB      8               // row blocks
#define ROWS_PER_RB (ROWS / RB) // 10240
#define CHUNK   1024            // rows staged per chunk

// Table: 5 groups of 8 bits (256 entries) + 1 group of 5 bits (32 entries)
// tab[q][e][c], q<5: offset q*8192 + e*32 + c ; group5 at 40960 + e*32 + c
#define TAB_FLOATS      41984                  // 5*256*32 + 32*32
#define SCRATCH_FLOATS  6560                   // max(Ht 1440 + s4 5120, rec 4096)
#define SMEM_FLOATS     (TAB_FLOATS + SCRATCH_FLOATS)
#define SMEM_BYTES      (SMEM_FLOATS * 4)      // 194176 B

// Scratch (allocation-free: __device__ globals)
__device__ uint4               g_rec[ROWS];                 // 16 B / row: 6 pre-scaled u16 offsets
__device__ unsigned long long  g_part[(size_t)ROWS * CT];   // per-(row, tile): key<<32 | (4095-col)

// ---------------------------------------------------------------------------
// Kernel 1: sign mask per row -> packed table offsets (pre-scaled by 128 B)
// y[c][k] = x0*S[c,0,k] + x1*S[c,1,k] - T[c,k] - 1e-4 ; bit p = (y < 0),
// p = cl*15 + k, row r = token*10 + g covers channels c = 3g..3g+2.
// ---------------------------------------------------------------------------
__global__ void k_signs(const float* __restrict__ x,
                        const float* __restrict__ S,
                        const float* __restrict__ T)
{
    int i = blockIdx.x * blockDim.x + threadIdx.x;
    if (i >= ROWS) return;
    int token = i / 10, g = i % 10;
    int a = token >> 3, b = token & 7;
    const float* xr = x + a * 480 + b * 60;

    unsigned long long mask = 0ull;
#pragma unroll
    for (int cl = 0; cl < 3; cl++) {
        int c = 3 * g + cl;
        float x0 = xr[c * 2 + 0];
        float x1 = xr[c * 2 + 1];
        const float* S0 = S + c * 30;        // S[c][0][*]
        const float* S1 = S0 + 15;           // S[c][1][*]
        const float* Tc = T + c * 15;
#pragma unroll
        for (int k = 0; k < 15; k++) {
            // match reference order/rounding (no fma contraction)
            float y = __fadd_rn(__fmul_rn(x0, S0[k]), __fmul_rn(x1, S1[k]));
            y = __fadd_rn(y, -Tc[k]);
            y = __fadd_rn(y, -1e-4f);
            if (y < 0.f) mask |= 1ull << (cl * 15 + k);
        }
    }

    unsigned o0 = (unsigned)((mask       ) & 255u) << 7;   // e * 128 bytes
    unsigned o1 = (unsigned)((mask >>  8u) & 255u) << 7;
    unsigned o2 = (unsigned)((mask >> 16u) & 255u) << 7;
    unsigned o3 = (unsigned)((mask >> 24u) & 255u) << 7;
    unsigned o4 = (unsigned)((mask >> 32u) & 255u) << 7;
    unsigned o5 = (unsigned)((mask >> 40u) &  31u) << 7;

    g_rec[i] = make_uint4(o0 | (o1 << 16), o2 | (o3 << 16), o4 | (o5 << 16), 0u);
}

// ---------------------------------------------------------------------------
// Kernel 2: build sign-sum tables in SMEM, then scores + fused argmax.
// grid = 1024 CTAs: bid&127 = col tile (32 cols), bid>>7 = row block.
// One warp per row per 32-col tile: lane = column; row records staged in
// SMEM chunks so the hot loop is pure LDS + FADD + REDUX.
// ---------------------------------------------------------------------------
__global__ __launch_bounds__(1024, 1)
void k_scores(const float* __restrict__ H)
{
    extern __shared__ float smem[];
    float* tab     = smem;                   // [41984]
    float* scratch = smem + TAB_FLOATS;      // build: Ht[1440] + s4[5120]; run: rec[1024] uint4

    const int ct = blockIdx.x & (CT - 1);
    const int rb = blockIdx.x >> 7;
    const int colbase = ct * JT;
    const int tid = threadIdx.x;

    float* Ht = scratch;                     // [45][32]
    float* s4 = scratch + 1440;              // [5][2][16][32]

    // Phase A: stage the 45 x 32 slice of H
    for (int i = tid; i < 45 * JT; i += 1024)
        Ht[i] = H[(size_t)(i >> 5) * NCOLS + colbase + (i & 31)];
    __syncthreads();

    // Phase B: 4-bit sub-tables for the five 8-bit groups + direct 5-bit group
    for (int idx = tid; idx < 6144; idx += 1024) {
        if (idx < 5120) {
            int c = idx & 31, e = (idx >> 5) & 15, h = (idx >> 9) & 1, q = idx >> 10;
            const float* hp = Ht + (q * 8 + h * 4) * JT + c;
            float acc = (e & 1) ? -hp[0] : hp[0];
            acc += (e & 2) ? -hp[JT]     : hp[JT];
            acc += (e & 4) ? -hp[2 * JT] : hp[2 * JT];
            acc += (e & 8) ? -hp[3 * JT] : hp[3 * JT];
            s4[(q * 2 + h) * 512 + e * JT + c] = acc;
        } else {
            int j = idx - 5120;
            int c = j & 31, e = j >> 5;      // e in 0..31
            const float* hp = Ht + 40 * JT + c;
            float acc = (e & 1) ? -hp[0] : hp[0];
            acc += (e &  2) ? -hp[JT]     : hp[JT];
            acc += (e &  4) ? -hp[2 * JT] : hp[2 * JT];
            acc += (e &  8) ? -hp[3 * JT] : hp[3 * JT];
            acc += (e & 16) ? -hp[4 * JT] : hp[4 * JT];
            tab[40960 + e * JT + c] = acc;
        }
    }
    __syncthreads();

    // Phase C: combine sub-tables -> 256-entry tables (2 LDS + 1 FADD each)
    for (int idx = tid; idx < 40960; idx += 1024) {
        int c = idx & 31, e = (idx >> 5) & 255, q = idx >> 13;
        tab[idx] = s4[(q * 2) * 512 + (e & 15) * JT + c]
                 + s4[(q * 2 + 1) * 512 + (e >> 4) * JT + c];
    }

    // Main loop setup
    const int warp = tid >> 5, lane = tid & 31;
    const char* tb = (const char*)tab;
    const char* b0 = tb + lane * 4;
    const char* b1 = b0 + 1 * 32768;
    const char* b2 = b0 + 2 * 32768;
    const char* b3 = b0 + 3 * 32768;
    const char* b4 = b0 + 4 * 32768;
    const char* b5 = b0 + 5 * 32768;        // group5 base = 40960 floats = 163840 B
    const unsigned loCol = (unsigned)(4095 - (colbase + lane));  // max picks SMALLEST col
    const bool isL0 = (lane == 0);
    const uint4* recbuf = (const uint4*)scratch;  // aliases build scratch

    const int rowBase = rb * ROWS_PER_RB;

    for (int ch = 0; ch < ROWS_PER_RB / CHUNK; ch++) {
        int chBase = rowBase + ch * CHUNK;
        __syncthreads();                      // protect recbuf reuse
        ((uint4*)scratch)[tid] = g_rec[chBase + tid];
        __syncthreads();

        unsigned long long* outp = g_part + (size_t)chBase * CT + ct;

#pragma unroll 4
        for (int i = warp; i < CHUNK; i += 32) {
            uint4 rc = recbuf[i];
            float v0 = *(const float*)(b0 + (rc.x & 0xFFFFu));
            float v1 = *(const float*)(b1 + (rc.x >> 16));
            float v2 = *(const float*)(b2 + (rc.y & 0xFFFFu));
            float v3 = *(const float*)(b3 + (rc.y >> 16));
            float v4 = *(const float*)(b4 + (rc.z & 0xFFFFu));
            float v5 = *(const float*)(b5 + (rc.z >> 16));
            float s = ((v0 + v1) + (v2 + v3)) + (v4 + v5);

            unsigned u   = __float_as_uint(s);
            unsigned key = u ^ (unsigned)(((int)u >> 31) | 0x80000000);
            unsigned m    = __reduce_max_sync(0xffffffffu, key);
            unsigned cand = (key == m) ? loCol : 0u;
            unsigned c2   = __reduce_max_sync(0xffffffffu, cand);
            if (isL0)
                outp[(size_t)i * CT] = ((unsigned long long)m << 32) | (unsigned long long)c2;
        }
    }
}

// ---------------------------------------------------------------------------
// Kernel 3: merge 128 tile-winners per row, gather LUT, write output.
// One warp per row; lane loads 4 partials.
// ---------------------------------------------------------------------------
__global__ void k_merge(const float* __restrict__ LUT, float2* __restrict__ out)
{
    int wg   = (blockIdx.x * blockDim.x + threadIdx.x) >> 5;
    int lane = threadIdx.x & 31;
    if (wg >= ROWS) return;

    const unsigned long long* p = g_part + (size_t)wg * CT;
    unsigned long long best = p[lane];
    unsigned long long t;
    t = p[lane + 32]; if (t > best) best = t;
    t = p[lane + 64]; if (t > best) best = t;
    t = p[lane + 96]; if (t > best) best = t;

    unsigned hi = (unsigned)(best >> 32);
    unsigned lo = (unsigned)best;
    unsigned mhi  = __reduce_max_sync(0xffffffffu, hi);
    unsigned cand = (hi == mhi) ? lo : 0u;
    unsigned mlo  = __reduce_max_sync(0xffffffffu, cand);

    if (lane == 0) {
        int col = 4095 - (int)mlo;
        int g   = wg % 10;
        const float2* l2 = reinterpret_cast<const float2*>(LUT);
        out[wg] = l2[(size_t)g * NCOLS + col];
    }
}

// ---------------------------------------------------------------------------
extern "C" void kernel_launch(void* const* d_in, const int* in_sizes, int n_in,
                              void* d_out, int out_size)
{
    const float* x   = (const float*)d_in[0];
    const float* S   = (const float*)d_in[1];
    const float* T   = (const float*)d_in[2];
    const float* H   = (const float*)d_in[3];
    const float* LUT = (const float*)d_in[4];
    (void)in_sizes; (void)n_in; (void)out_size;

    cudaFuncSetAttribute(k_scores, cudaFuncAttributeMaxDynamicSharedMemorySize, SMEM_BYTES);

    k_signs<<<(ROWS + 255) / 256, 256>>>(x, S, T);
    k_scores<<<CT * RB, 1024, SMEM_BYTES>>>(H);
    k_merge<<<(ROWS * 32 + 255) / 256, 256>>>(LUT, (float2*)d_out);
}

// round 6
// speedup vs baseline: 3.4727x; 1.0001x over previous
#include <cuda_runtime.h>
#include <cstdint>

// ---------------------------------------------------------------------------
// Problem constants
// ---------------------------------------------------------------------------
#define NTOK    8192            // 1024 * 8 tokens
#define ROWS    81920           // NTOK * 10 groups
#define NCOLS   4096
#define CT      128             // column tiles of 32
#define JT      32              // columns per tile
#define RB      8               // row blocks
#define ROWS_PER_RB (ROWS / RB) // 10240
#define CHUNK   1024            // rows staged per chunk

// Table: 5 groups of 8 bits (256 entries) + 1 group of 5 bits (32 entries)
// tab[q][e][c], q<5: offset q*8192 + e*32 + c ; group5 at 40960 + e*32 + c
#define TAB_FLOATS      41984                  // 5*256*32 + 32*32
#define SCRATCH_FLOATS  6560                   // max(Ht 1440 + s4 5120, rec 4096)
#define SMEM_FLOATS     (TAB_FLOATS + SCRATCH_FLOATS)
#define SMEM_BYTES      (SMEM_FLOATS * 4)      // 194176 B

// Scratch (allocation-free: __device__ globals)
__device__ uint4               g_rec[ROWS];                 // 16 B / row: 6 pre-scaled u16 offsets
__device__ unsigned long long  g_part[(size_t)ROWS * CT];   // per-(row, tile): key<<32 | (4095-col)

// ---------------------------------------------------------------------------
// Kernel 1: sign mask per row -> packed table offsets (pre-scaled by 128 B)
// y[c][k] = x0*S[c,0,k] + x1*S[c,1,k] - T[c,k] - 1e-4 ; bit p = (y < 0),
// p = cl*15 + k, row r = token*10 + g covers channels c = 3g..3g+2.
// ---------------------------------------------------------------------------
__global__ void k_signs(const float* __restrict__ x,
                        const float* __restrict__ S,
                        const float* __restrict__ T)
{
    int i = blockIdx.x * blockDim.x + threadIdx.x;
    if (i >= ROWS) return;
    int token = i / 10, g = i % 10;
    int a = token >> 3, b = token & 7;
    const float* xr = x + a * 480 + b * 60;

    unsigned long long mask = 0ull;
#pragma unroll
    for (int cl = 0; cl < 3; cl++) {
        int c = 3 * g + cl;
        float x0 = xr[c * 2 + 0];
        float x1 = xr[c * 2 + 1];
        const float* S0 = S + c * 30;        // S[c][0][*]
        const float* S1 = S0 + 15;           // S[c][1][*]
        const float* Tc = T + c * 15;
#pragma unroll
        for (int k = 0; k < 15; k++) {
            // match reference order/rounding (no fma contraction)
            float y = __fadd_rn(__fmul_rn(x0, S0[k]), __fmul_rn(x1, S1[k]));
            y = __fadd_rn(y, -Tc[k]);
            y = __fadd_rn(y, -1e-4f);
            if (y < 0.f) mask |= 1ull << (cl * 15 + k);
        }
    }

    unsigned o0 = (unsigned)((mask       ) & 255u) << 7;   // e * 128 bytes
    unsigned o1 = (unsigned)((mask >>  8u) & 255u) << 7;
    unsigned o2 = (unsigned)((mask >> 16u) & 255u) << 7;
    unsigned o3 = (unsigned)((mask >> 24u) & 255u) << 7;
    unsigned o4 = (unsigned)((mask >> 32u) & 255u) << 7;
    unsigned o5 = (unsigned)((mask >> 40u) &  31u) << 7;

    g_rec[i] = make_uint4(o0 | (o1 << 16), o2 | (o3 << 16), o4 | (o5 << 16), 0u);
}

// ---------------------------------------------------------------------------
// Kernel 2: build sign-sum tables in SMEM, then scores + fused argmax.
// grid = 1024 CTAs: bid&127 = col tile (32 cols), bid>>7 = row block.
// One warp per row per 32-col tile: lane = column; row records staged in
// SMEM chunks so the hot loop is pure LDS + FADD + REDUX.
// ---------------------------------------------------------------------------
__global__ __launch_bounds__(1024, 1)
void k_scores(const float* __restrict__ H)
{
    extern __shared__ float smem[];
    float* tab     = smem;                   // [41984]
    float* scratch = smem + TAB_FLOATS;      // build: Ht[1440] + s4[5120]; run: rec[1024] uint4

    const int ct = blockIdx.x & (CT - 1);
    const int rb = blockIdx.x >> 7;
    const int colbase = ct * JT;
    const int tid = threadIdx.x;

    float* Ht = scratch;                     // [45][32]
    float* s4 = scratch + 1440;              // [5][2][16][32]

    // Phase A: stage the 45 x 32 slice of H
    for (int i = tid; i < 45 * JT; i += 1024)
        Ht[i] = H[(size_t)(i >> 5) * NCOLS + colbase + (i & 31)];
    __syncthreads();

    // Phase B: 4-bit sub-tables for the five 8-bit groups + direct 5-bit group
    for (int idx = tid; idx < 6144; idx += 1024) {
        if (idx < 5120) {
            int c = idx & 31, e = (idx >> 5) & 15, h = (idx >> 9) & 1, q = idx >> 10;
            const float* hp = Ht + (q * 8 + h * 4) * JT + c;
            float acc = (e & 1) ? -hp[0] : hp[0];
            acc += (e & 2) ? -hp[JT]     : hp[JT];
            acc += (e & 4) ? -hp[2 * JT] : hp[2 * JT];
            acc += (e & 8) ? -hp[3 * JT] : hp[3 * JT];
            s4[(q * 2 + h) * 512 + e * JT + c] = acc;
        } else {
            int j = idx - 5120;
            int c = j & 31, e = j >> 5;      // e in 0..31
            const float* hp = Ht + 40 * JT + c;
            float acc = (e & 1) ? -hp[0] : hp[0];
            acc += (e &  2) ? -hp[JT]     : hp[JT];
            acc += (e &  4) ? -hp[2 * JT] : hp[2 * JT];
            acc += (e &  8) ? -hp[3 * JT] : hp[3 * JT];
            acc += (e & 16) ? -hp[4 * JT] : hp[4 * JT];
            tab[40960 + e * JT + c] = acc;
        }
    }
    __syncthreads();

    // Phase C: combine sub-tables -> 256-entry tables (2 LDS + 1 FADD each)
    for (int idx = tid; idx < 40960; idx += 1024) {
        int c = idx & 31, e = (idx >> 5) & 255, q = idx >> 13;
        tab[idx] = s4[(q * 2) * 512 + (e & 15) * JT + c]
                 + s4[(q * 2 + 1) * 512 + (e >> 4) * JT + c];
    }

    // Main loop setup
    const int warp = tid >> 5, lane = tid & 31;
    const char* tb = (const char*)tab;
    const char* b0 = tb + lane * 4;
    const char* b1 = b0 + 1 * 32768;
    const char* b2 = b0 + 2 * 32768;
    const char* b3 = b0 + 3 * 32768;
    const char* b4 = b0 + 4 * 32768;
    const char* b5 = b0 + 5 * 32768;        // group5 base = 40960 floats = 163840 B
    const unsigned loCol = (unsigned)(4095 - (colbase + lane));  // max picks SMALLEST col
    const bool isL0 = (lane == 0);
    const uint4* recbuf = (const uint4*)scratch;  // aliases build scratch

    const int rowBase = rb * ROWS_PER_RB;

    for (int ch = 0; ch < ROWS_PER_RB / CHUNK; ch++) {
        int chBase = rowBase + ch * CHUNK;
        __syncthreads();                      // protect recbuf reuse
        ((uint4*)scratch)[tid] = g_rec[chBase + tid];
        __syncthreads();

        unsigned long long* outp = g_part + (size_t)chBase * CT + ct;

#pragma unroll 4
        for (int i = warp; i < CHUNK; i += 32) {
            uint4 rc = recbuf[i];
            float v0 = *(const float*)(b0 + (rc.x & 0xFFFFu));
            float v1 = *(const float*)(b1 + (rc.x >> 16));
            float v2 = *(const float*)(b2 + (rc.y & 0xFFFFu));
            float v3 = *(const float*)(b3 + (rc.y >> 16));
            float v4 = *(const float*)(b4 + (rc.z & 0xFFFFu));
            float v5 = *(const float*)(b5 + (rc.z >> 16));
            float s = ((v0 + v1) + (v2 + v3)) + (v4 + v5);

            unsigned u   = __float_as_uint(s);
            unsigned key = u ^ (unsigned)(((int)u >> 31) | 0x80000000);
            unsigned m    = __reduce_max_sync(0xffffffffu, key);
            unsigned cand = (key == m) ? loCol : 0u;
            unsigned c2   = __reduce_max_sync(0xffffffffu, cand);
            if (isL0)
                outp[(size_t)i * CT] = ((unsigned long long)m << 32) | (unsigned long long)c2;
        }
    }
}

// ---------------------------------------------------------------------------
// Kernel 3: merge 128 tile-winners per row, gather LUT, write output.
// One warp per row; lane loads 4 partials.
// ---------------------------------------------------------------------------
__global__ void k_merge(const float* __restrict__ LUT, float2* __restrict__ out)
{
    int wg   = (blockIdx.x * blockDim.x + threadIdx.x) >> 5;
    int lane = threadIdx.x & 31;
    if (wg >= ROWS) return;

    const unsigned long long* p = g_part + (size_t)wg * CT;
    unsigned long long best = p[lane];
    unsigned long long t;
    t = p[lane + 32]; if (t > best) best = t;
    t = p[lane + 64]; if (t > best) best = t;
    t = p[lane + 96]; if (t > best) best = t;

    unsigned hi = (unsigned)(best >> 32);
    unsigned lo = (unsigned)best;
    unsigned mhi  = __reduce_max_sync(0xffffffffu, hi);
    unsigned cand = (hi == mhi) ? lo : 0u;
    unsigned mlo  = __reduce_max_sync(0xffffffffu, cand);

    if (lane == 0) {
        int col = 4095 - (int)mlo;
        int g   = wg % 10;
        const float2* l2 = reinterpret_cast<const float2*>(LUT);
        out[wg] = l2[(size_t)g * NCOLS + col];
    }
}

// ---------------------------------------------------------------------------
extern "C" void kernel_launch(void* const* d_in, const int* in_sizes, int n_in,
                              void* d_out, int out_size)
{
    const float* x   = (const float*)d_in[0];
    const float* S   = (const float*)d_in[1];
    const float* T   = (const float*)d_in[2];
    const float* H   = (const float*)d_in[3];
    const float* LUT = (const float*)d_in[4];
    (void)in_sizes; (void)n_in; (void)out_size;

    cudaFuncSetAttribute(k_scores, cudaFuncAttributeMaxDynamicSharedMemorySize, SMEM_BYTES);

    k_signs<<<(ROWS + 255) / 256, 256>>>(x, S, T);
    k_scores<<<CT * RB, 1024, SMEM_BYTES>>>(H);
    k_merge<<<(ROWS * 32 + 255) / 256, 256>>>(LUT, (float2*)d_out);
}

// round 8
// speedup vs baseline: 4.0631x; 1.1700x over previous
#include <cuda_runtime.h>
#include <cuda_bf16.h>
#include <cstdint>

#define ROWS   81920
#define NCOLS  4096
#define KG     144              // padded K (135 real = 3*45), 9 k16 steps
#define ROWB   288              // global row bytes (144 bf16)
#define SSTR   304              // smem row stride bytes (19 x 16B -> conflict-free ldmatrix)
#define TPC    8                // M-tiles per CTA
#define MSLOTS 80
#define NT     32               // 4096 / 128 N-tiles

// SMEM: B tile 128x304 = 38912 ; A double buffer 2 x 38912
#define SM_B   0
#define SM_A0  38912
#define SM_A1  77824
#define SM_TOT 116736

__device__ __align__(16) __nv_bfloat16 g_Y [(size_t)ROWS  * KG];   // 23.6 MB
__device__ __align__(16) __nv_bfloat16 g_Hb[(size_t)NCOLS * KG];   // 1.2 MB
__device__ unsigned long long          g_part[(size_t)ROWS * 64];  // winners per (row, ntile, wn)

// ---------------- helpers ----------------
__device__ __forceinline__ uint32_t smem_u32(const void* p) {
    uint32_t a;
    asm("{ .reg .u64 t; cvta.to.shared.u64 t, %1; cvt.u32.u64 %0, t; }" : "=r"(a) : "l"(p));
    return a;
}
__device__ __forceinline__ void cpasync16(uint32_t dst, const void* src) {
    asm volatile("cp.async.cg.shared.global [%0], [%1], 16;" :: "r"(dst), "l"(src) : "memory");
}
#define CP_COMMIT() asm volatile("cp.async.commit_group;" ::: "memory")
#define CP_WAIT0()  asm volatile("cp.async.wait_group 0;" ::: "memory")

#define LDX4(d, addr)                                                              \
    asm volatile("ldmatrix.sync.aligned.m8n8.x4.shared.b16 {%0,%1,%2,%3}, [%4];"   \
        : "=r"((d)[0]), "=r"((d)[1]), "=r"((d)[2]), "=r"((d)[3]) : "r"(addr))

#define MMA(c, a, b0, b1)                                                          \
    asm volatile("mma.sync.aligned.m16n8k16.row.col.f32.bf16.bf16.f32 "            \
        "{%0,%1,%2,%3}, {%4,%5,%6,%7}, {%8,%9}, {%0,%1,%2,%3};"                    \
        : "+f"((c)[0]), "+f"((c)[1]), "+f"((c)[2]), "+f"((c)[3])                   \
        : "r"((a)[0]), "r"((a)[1]), "r"((a)[2]), "r"((a)[3]), "r"(b0), "r"(b1))

// ---------------------------------------------------------------------------
// K1: sign masks -> Y rows (bf16 ±1, K=144 = [y|y|y|9 zeros])
// ---------------------------------------------------------------------------
__global__ void k_signs(const float* __restrict__ x,
                        const float* __restrict__ S,
                        const float* __restrict__ T)
{
    int i = blockIdx.x * blockDim.x + threadIdx.x;
    if (i >= ROWS) return;
    int token = i / 10, g = i % 10;
    const float* xr = x + (token >> 3) * 480 + (token & 7) * 60;

    unsigned long long mask = 0ull;
#pragma unroll
    for (int cl = 0; cl < 3; cl++) {
        int c = 3 * g + cl;
        float x0 = xr[c * 2 + 0], x1 = xr[c * 2 + 1];
        const float* S0 = S + c * 30;
        const float* S1 = S0 + 15;
        const float* Tc = T + c * 15;
#pragma unroll
        for (int k = 0; k < 15; k++) {
            float y = __fadd_rn(__fmul_rn(x0, S0[k]), __fmul_rn(x1, S1[k]));
            y = __fadd_rn(y, -Tc[k]);
            y = __fadd_rn(y, -1e-4f);
            if (y < 0.f) mask |= 1ull << (cl * 15 + k);
        }
    }

    uint4* yp = reinterpret_cast<uint4*>(g_Y + (size_t)i * KG);
#pragma unroll
    for (int q = 0; q < 18; q++) {
        unsigned w[4];
#pragma unroll
        for (int e = 0; e < 4; e++) {
            int p0 = q * 8 + e * 2, p1 = p0 + 1;
            unsigned lo = 0, hi = 0;
            if (p0 < 135) lo = 0x3F80u | ((unsigned)((mask >> (p0 % 45)) & 1ull) << 15);
            if (p1 < 135) hi = 0x3F80u | ((unsigned)((mask >> (p1 % 45)) & 1ull) << 15);
            w[e] = lo | (hi << 16);
        }
        yp[q] = make_uint4(w[0], w[1], w[2], w[3]);
    }
}

// ---------------------------------------------------------------------------
// K2: exact 3-way bf16 split of H -> g_Hb[n][k], k = j*45 + d, pad zeroed
// ---------------------------------------------------------------------------
__global__ void k_hconv(const float* __restrict__ H)
{
    int n = blockIdx.x * blockDim.x + threadIdx.x;
    if (n >= NCOLS) return;
    __nv_bfloat16* row = g_Hb + (size_t)n * KG;
    for (int d = 0; d < 45; d++) {
        float h = H[(size_t)d * NCOLS + n];
        __nv_bfloat16 b1 = __float2bfloat16(h);
        float r1 = h - __bfloat162float(b1);
        __nv_bfloat16 b2 = __float2bfloat16(r1);
        float r2 = r1 - __bfloat162float(b2);
        row[d] = b1; row[45 + d] = b2; row[90 + d] = __float2bfloat16(r2);
    }
    for (int p = 135; p < KG; p++) row[p] = __float2bfloat16(0.f);
}

// ---------------------------------------------------------------------------
// K3: mma.sync GEMM + register argmax epilogue.
// grid 2560: ntile = bid & 31 (128 cols), mslot = bid >> 5 (8 M-tiles of 128).
// ---------------------------------------------------------------------------
__device__ __forceinline__ void load_A(uint32_t dst, int grow0, int tid)
{
    const char* src = (const char*)g_Y + (size_t)grow0 * ROWB;
#pragma unroll
    for (int it = 0; it < 9; it++) {
        int c = tid + it * 256;                  // 2304 chunks: 128 rows x 18
        int r = c / 18, kc = c - r * 18;
        cpasync16(dst + (uint32_t)(r * SSTR + kc * 16), src + (size_t)r * ROWB + kc * 16);
    }
}

__global__ void __launch_bounds__(256, 1) k_gemm()
{
    extern __shared__ char smem[];
    uint32_t sb = smem_u32(smem);
    const int tid = threadIdx.x, wid = tid >> 5, lane = tid & 31;
    const int ntile = blockIdx.x & 31;
    const int mslot = blockIdx.x >> 5;
    const int wm = wid >> 1, wn = wid & 1;       // warp grid 4(m) x 2(n)

    // B tile: 128 n-rows x 144 k (resident)
    {
        const char* hb = (const char*)g_Hb + (size_t)(ntile * 128) * ROWB;
#pragma unroll
        for (int it = 0; it < 9; it++) {
            int c = tid + it * 256;
            int r = c / 18, kc = c - r * 18;
            cpasync16(sb + SM_B + (uint32_t)(r * SSTR + kc * 16), hb + (size_t)r * ROWB + kc * 16);
        }
    }
    load_A(sb + SM_A0, mslot * TPC * 128, tid);
    CP_COMMIT();

    // ldmatrix lane offsets
    const int j = lane >> 3, lr = lane & 7;
    const uint32_t aoff = (uint32_t)((wm * 32 + (j & 1) * 8 + lr) * SSTR + (j >> 1) * 16);
    const uint32_t boff = sb + SM_B + (uint32_t)((wn * 64 + (j >> 1) * 8 + lr) * SSTR + (j & 1) * 16);
    const int lq = lane & 3;                     // column sub-lane
    const int lrow = lane >> 2;                  // row within m16

    for (int i = 0; i < TPC; i++) {
        const int b = i & 1;
        CP_WAIT0();                              // A(i) (and B at i=0) resident
        __syncthreads();
        if (i < TPC - 1) {                       // prefetch A(i+1) into other buffer
            load_A(sb + (b ? SM_A0 : SM_A1), (mslot * TPC + i + 1) * 128, tid);
            CP_COMMIT();
        }

        const uint32_t abase = sb + (b ? SM_A1 : SM_A0) + aoff;
        float acc[2][8][4];
#pragma unroll
        for (int mb = 0; mb < 2; mb++)
#pragma unroll
            for (int nb = 0; nb < 8; nb++)
#pragma unroll
                for (int e = 0; e < 4; e++) acc[mb][nb][e] = 0.f;

#pragma unroll
        for (int ks = 0; ks < 9; ks++) {
            uint32_t a0[4], a1[4], bb[4][4];
            LDX4(a0, abase + ks * 32);
            LDX4(a1, abase + ks * 32 + 16 * SSTR);
#pragma unroll
            for (int n16 = 0; n16 < 4; n16++)
                LDX4(bb[n16], boff + (uint32_t)(n16 * 16 * SSTR) + ks * 32);
#pragma unroll
            for (int nb = 0; nb < 8; nb++) {
                const uint32_t* bp = bb[nb >> 1];
                uint32_t blo = (nb & 1) ? bp[2] : bp[0];
                uint32_t bhi = (nb & 1) ? bp[3] : bp[1];
                MMA(acc[0][nb], a0, blo, bhi);
                MMA(acc[1][nb], a1, blo, bhi);
            }
        }

        // Epilogue: per (mb, h) row argmax over this warp's 64 columns
        const int rowbase = (mslot * TPC + i) * 128 + wm * 32 + lrow;
        const int colbase = ntile * 128 + wn * 64 + 2 * lq;
#pragma unroll
        for (int mb = 0; mb < 2; mb++) {
#pragma unroll
            for (int h = 0; h < 2; h++) {
                float bv = -__int_as_float(0x7f800000);   // -inf
                int   bc = 0;
#pragma unroll
                for (int nb = 0; nb < 8; nb++) {
                    float v0 = acc[mb][nb][2 * h];
                    float v1 = acc[mb][nb][2 * h + 1];
                    int c0 = colbase + nb * 8;
                    if (v0 > bv) { bv = v0; bc = c0; }       // strict >: first index
                    if (v1 > bv) { bv = v1; bc = c0 + 1; }
                }
                unsigned u   = __float_as_uint(bv);
                unsigned key = u ^ (unsigned)(((int)u >> 31) | 0x80000000);
                unsigned long long pk =
                    ((unsigned long long)key << 32) | (unsigned long long)(4095u - (unsigned)bc);
#pragma unroll
                for (int off = 1; off < 4; off <<= 1) {
                    unsigned long long o = __shfl_xor_sync(0xffffffffu, pk, off);
                    if (o > pk) pk = o;
                }
                if (lq == 0) {
                    int row = rowbase + mb * 16 + h * 8;
                    g_part[(size_t)row * 64 + ntile * 2 + wn] = pk;
                }
            }
        }
    }
}

// ---------------------------------------------------------------------------
// K4: merge 64 winners per row, LUT gather, write out
// ---------------------------------------------------------------------------
__global__ void k_merge(const float* __restrict__ LUT, float2* __restrict__ out)
{
    int wg   = (blockIdx.x * blockDim.x + threadIdx.x) >> 5;
    int lane = threadIdx.x & 31;
    if (wg >= ROWS) return;

    const unsigned long long* p = g_part + (size_t)wg * 64;
    unsigned long long v = p[lane];
    unsigned long long w = p[lane + 32];
    if (w > v) v = w;

    unsigned hi = (unsigned)(v >> 32);
    unsigned lo = (unsigned)v;
    unsigned mhi  = __reduce_max_sync(0xffffffffu, hi);
    unsigned cand = (hi == mhi) ? lo : 0u;
    unsigned mlo  = __reduce_max_sync(0xffffffffu, cand);

    if (lane == 0) {
        int col = 4095 - (int)mlo;
        int g   = wg % 10;
        const float2* l2 = reinterpret_cast<const float2*>(LUT);
        out[wg] = l2[(size_t)g * NCOLS + col];
    }
}

// ---------------------------------------------------------------------------
extern "C" void kernel_launch(void* const* d_in, const int* in_sizes, int n_in,
                              void* d_out, int out_size)
{
    const float* x   = (const float*)d_in[0];
    const float* S   = (const float*)d_in[1];
    const float* T   = (const float*)d_in[2];
    const float* H   = (const float*)d_in[3];
    const float* LUT = (const float*)d_in[4];
    (void)in_sizes; (void)n_in; (void)out_size;

    cudaFuncSetAttribute(k_gemm, cudaFuncAttributeMaxDynamicSharedMemorySize, SM_TOT);

    k_signs<<<(ROWS + 255) / 256, 256>>>(x, S, T);
    k_hconv<<<NCOLS / 256, 256>>>(H);
    k_gemm<<<MSLOTS * NT, 256, SM_TOT>>>();
    k_merge<<<(ROWS * 32 + 255) / 256, 256>>>(LUT, (float2*)d_out);
}